// round 16
// baseline (speedup 1.0000x reference)
#include <cuda_runtime.h>
#include <cuda_bf16.h>
#include <cuda_fp16.h>
#include <cstdint>

// ---------------------------------------------------------------------------
// Problem constants
// ---------------------------------------------------------------------------
#define BB 4
#define SS 8192
#define DD 1024
#define MM (BB * SS)      // 32768
#define N3 (3 * DD)       // 3072

// Scan chunking
#define SCAN_C 32
#define SCAN_L (SS / SCAN_C)   // 256
#define NCH (BB * DD)          // 4096

// GEMM tiling (R6/R14 pipeline protocol; warp grid 2x4 under test)
#define TMT 128            // CTA M tile
#define TNT 64             // CTA N (d) tile per gate
#define KC 64              // fp16 K per chunk (128B rows)
#define NCHUNK 16          // single pass over K=1024
#define ROWB 144           // padded row bytes (128 data + 16 pad) -> conflict-free ldmatrix
#define A_BYTES (TMT * ROWB)          // 18432
#define BG_BYTES (TNT * ROWB)         // 9216
#define STAGEB (A_BYTES + 3 * BG_BYTES)  // 46080
#define DYN_BYTES (2 * STAGEB)        // 92160

// ---------------------------------------------------------------------------
// Scratch (static device allocations)
// ---------------------------------------------------------------------------
__device__ __half g_xh[(size_t)MM * DD];
__device__ __half g_wh[(size_t)N3 * DD];          // transposed: [n][k]
__device__ __half2 g_fv[(size_t)MM * DD];         // packed (f', val) per element
__device__ float g_pF[SCAN_C * NCH];
__device__ float g_pH[SCAN_C * NCH];
__device__ float g_carry[SCAN_C * NCH];

// ---------------------------------------------------------------------------
// Portable PTX helpers (valid on plain sm_103 target)
// ---------------------------------------------------------------------------
__device__ __forceinline__ uint32_t smem_u32(const void* p) {
    uint32_t a;
    asm("{ .reg .u64 t; cvta.to.shared.u64 t, %1; cvt.u32.u64 %0, t; }" : "=r"(a) : "l"(p));
    return a;
}
__device__ __forceinline__ void cpa16(uint32_t s, const void* g) {
    asm volatile("cp.async.cg.shared.global [%0], [%1], 16;" :: "r"(s), "l"(g));
}
__device__ __forceinline__ void ldmatrix_x4(uint32_t* r, uint32_t addr) {
    asm volatile("ldmatrix.sync.aligned.m8n8.x4.shared.b16 {%0,%1,%2,%3}, [%4];"
                 : "=r"(r[0]), "=r"(r[1]), "=r"(r[2]), "=r"(r[3]) : "r"(addr));
}
__device__ __forceinline__ void mma_fp16(float* c, const uint32_t* a, uint32_t b0, uint32_t b1) {
    asm volatile(
        "mma.sync.aligned.m16n8k16.row.col.f32.f16.f16.f32 "
        "{%0,%1,%2,%3}, {%4,%5,%6,%7}, {%8,%9}, {%0,%1,%2,%3};"
        : "+f"(c[0]), "+f"(c[1]), "+f"(c[2]), "+f"(c[3])
        : "r"(a[0]), "r"(a[1]), "r"(a[2]), "r"(a[3]), "r"(b0), "r"(b1));
}

// ---------------------------------------------------------------------------
// Convert X -> fp16
// ---------------------------------------------------------------------------
__global__ __launch_bounds__(256) void convert_x_kernel(const float* __restrict__ X) {
    size_t i = (size_t)blockIdx.x * blockDim.x + threadIdx.x;   // float4 index
    float4 v = ((const float4*)X)[i];
    __half2* ph = (__half2*)g_xh;
    ph[2 * i]     = __floats2half2_rn(v.x, v.y);
    ph[2 * i + 1] = __floats2half2_rn(v.z, v.w);
}

// ---------------------------------------------------------------------------
// Convert + transpose W [K=1024, N=3072] -> Wt [N=3072, K=1024] fp16
// ---------------------------------------------------------------------------
__global__ __launch_bounds__(256) void convert_w_kernel(const float* __restrict__ W) {
    __shared__ float tile[32][33];
    int bx = blockIdx.x;   // n tile (96)
    int by = blockIdx.y;   // k tile (32)
    int tx = threadIdx.x;  // 32
    int ty = threadIdx.y;  // 8
#pragma unroll
    for (int i = 0; i < 4; ++i) {
        int k = by * 32 + ty + i * 8;
        tile[ty + i * 8][tx] = W[(size_t)k * N3 + bx * 32 + tx];
    }
    __syncthreads();
#pragma unroll
    for (int i = 0; i < 4; ++i) {
        int n = bx * 32 + ty + i * 8;
        int k = by * 32 + tx;
        g_wh[(size_t)n * DD + k] = __float2half_rn(tile[tx][ty + i * 8]);
    }
}

// ---------------------------------------------------------------------------
// Issue cp.async loads for one K-chunk (KC=64 -> 128B per row) into a stage.
// ---------------------------------------------------------------------------
__device__ __forceinline__ void load_chunk(int c, uint32_t sb, int tid, int m0, int n0) {
    const int kk = c * KC;

    // A: 128 rows x 128B (1024 x 16B, 4 per thread)
#pragma unroll
    for (int it = 0; it < 4; ++it) {
        int id = tid + it * 256;
        int r = id >> 3, ch = id & 7;
        cpa16(sb + r * ROWB + ch * 16,
              g_xh + (size_t)(m0 + r) * DD + kk + ch * 8);
    }
    // B: 3 gates x 64 rows x 128B (512 x 16B per gate, 2 per thread)
#pragma unroll
    for (int g = 0; g < 3; ++g) {
#pragma unroll
        for (int it = 0; it < 2; ++it) {
            int id = tid + it * 256;
            int r = id >> 3, ch = id & 7;
            cpa16(sb + A_BYTES + g * BG_BYTES + r * ROWB + ch * 16,
                  g_wh + (size_t)(g * DD + n0 + r) * DD + kk + ch * 8);
        }
    }
    asm volatile("cp.async.commit_group;" ::: "memory");
}

// ---------------------------------------------------------------------------
// fp16 mma.sync GEMM + fused gate epilogue (linear domain).
// R6 protocol: double buffer, wait_group 1, MMA, sync, refill freed stage.
// CTA: 256 threads, warp grid 2(m) x 4(n): warp tile 64m x 16n per gate.
// ---------------------------------------------------------------------------
__global__ __launch_bounds__(256, 2) void gemm_gates_kernel() {
    extern __shared__ char sm_raw[];
    const uint32_t sbase = smem_u32(sm_raw);

    const int tid = threadIdx.x;
    const int wid = tid >> 5;
    const int lane = tid & 31;
    const int m0 = blockIdx.y * TMT;
    const int n0 = blockIdx.x * TNT;
    const int mw = (wid & 1) * 64;    // warp m offset (2 warps in m)
    const int nw = (wid >> 1) * 16;   // warp n offset (4 warps in n)

    // Per-lane ldmatrix address terms
    const int mat = lane >> 3;
    const uint32_t a_term = (uint32_t)((mw + (mat & 1) * 8 + (lane & 7)) * ROWB + (mat >> 1) * 16);
    const uint32_t b_term = (uint32_t)((nw + (mat >> 1) * 8 + (lane & 7)) * ROWB + (mat & 1) * 16);

    float acc[3][4][2][4];
#pragma unroll
    for (int g = 0; g < 3; ++g)
#pragma unroll
        for (int mt = 0; mt < 4; ++mt)
#pragma unroll
            for (int nt = 0; nt < 2; ++nt)
#pragma unroll
                for (int e = 0; e < 4; ++e) acc[g][mt][nt][e] = 0.0f;

    // Prologue: prefetch chunks 0,1
    load_chunk(0, sbase + 0 * STAGEB, tid, m0, n0);
    load_chunk(1, sbase + 1 * STAGEB, tid, m0, n0);

    for (int c = 0; c < NCHUNK; ++c) {
        asm volatile("cp.async.wait_group 1;" ::: "memory");
        __syncthreads();

        const uint32_t sb = sbase + (c & 1) * STAGEB;
#pragma unroll
        for (int ks = 0; ks < 4; ++ks) {
            // Preload ALL fragments for this ks (7 independent ldmatrix.x4),
            // then issue the 24 MMAs.
            uint32_t a[4][4];
            uint32_t b[3][4];
#pragma unroll
            for (int mt = 0; mt < 4; ++mt)
                ldmatrix_x4(a[mt], sb + a_term + mt * 16 * ROWB + ks * 32);
#pragma unroll
            for (int g = 0; g < 3; ++g)
                ldmatrix_x4(b[g], sb + A_BYTES + g * BG_BYTES + b_term + ks * 32);
#pragma unroll
            for (int g = 0; g < 3; ++g)
#pragma unroll
                for (int mt = 0; mt < 4; ++mt)
#pragma unroll
                    for (int nt = 0; nt < 2; ++nt)
                        mma_fp16(acc[g][mt][nt], a[mt], b[g][nt * 2], b[g][nt * 2 + 1]);
        }
        __syncthreads();   // all warps done reading this stage

        if (c + 2 < NCHUNK) {
            load_chunk(c + 2, sb, tid, m0, n0);   // refill the freed stage
        } else {
            asm volatile("cp.async.commit_group;" ::: "memory");
        }
    }

    // ------------------------------------------------------------------
    // Epilogue: gate math in linear domain, packed half2(f', val).
    //   u = 1+e^{-f}, v = 1+e^{-i}, r = 1/(u+v)
    //   f' = v*r, i' = u*r, g = (h>=0) ? h+0.5 : sigmoid(h), val = i'*g
    // ------------------------------------------------------------------
    const int rbase = lane >> 2;           // 0..7
    const int cbase = 2 * (lane & 3);      // 0,2,4,6
#pragma unroll
    for (int mt = 0; mt < 4; ++mt) {
#pragma unroll
        for (int nt = 0; nt < 2; ++nt) {
#pragma unroll
            for (int half = 0; half < 2; ++half) {
                const int m = m0 + mw + mt * 16 + rbase + half * 8;
                const int d = n0 + nw + nt * 8 + cbase;
                uint2 st;
#pragma unroll
                for (int e = 0; e < 2; ++e) {
                    const int ei = half * 2 + e;
                    float h  = acc[0][mt][nt][ei];
                    float fg = acc[1][mt][nt][ei];
                    float ig = acc[2][mt][nt][ei];
                    float u = 1.0f + __expf(-fg);
                    float v = 1.0f + __expf(-ig);
                    float r = __frcp_rn(u + v);
                    float fp = v * r;
                    float ip = u * r;
                    float eh = __expf(fminf(h, 0.0f));
                    float gneg = eh * __frcp_rn(1.0f + eh);
                    float gv = (h >= 0.0f) ? (h + 0.5f) : gneg;
                    __half2 pk = __floats2half2_rn(fp, ip * gv);
                    ((uint32_t*)&st)[e] = *(uint32_t*)&pk;
                }
                *(uint2*)&g_fv[(size_t)m * DD + d] = st;
            }
        }
    }
}

// ---------------------------------------------------------------------------
// Linear-domain scan on packed half2 (f', val): h = f*h + val
// ---------------------------------------------------------------------------
__global__ __launch_bounds__(1024) void scan_partial_kernel() {
    int d = threadIdx.x;
    int c = blockIdx.x;
    int b = blockIdx.y;
    size_t base = ((size_t)b * SS + (size_t)c * SCAN_L) * DD + d;
    float F = 1.0f;
    float H = 0.0f;
    for (int s = 0; s < SCAN_L; ++s) {
        float2 p = __half22float2(g_fv[base + (size_t)s * DD]);
        F *= p.x;
        H = fmaf(p.x, H, p.y);
    }
    int ch = b * DD + d;
    g_pF[c * NCH + ch] = F;
    g_pH[c * NCH + ch] = H;
}

__global__ __launch_bounds__(1024) void scan_combine_kernel() {
    int d = threadIdx.x;
    int b = blockIdx.x;
    int ch = b * DD + d;
    float st = 0.0f;
#pragma unroll
    for (int c = 0; c < SCAN_C; ++c) {
        g_carry[c * NCH + ch] = st;
        st = fmaf(g_pF[c * NCH + ch], st, g_pH[c * NCH + ch]);
    }
}

__global__ __launch_bounds__(1024) void scan_final_kernel(float* __restrict__ out) {
    int d = threadIdx.x;
    int c = blockIdx.x;
    int b = blockIdx.y;
    int ch = b * DD + d;
    float h = g_carry[c * NCH + ch];
    size_t base = ((size_t)b * SS + (size_t)c * SCAN_L) * DD + d;
    for (int s = 0; s < SCAN_L; ++s) {
        float2 p = __half22float2(g_fv[base + (size_t)s * DD]);
        h = fmaf(p.x, h, p.y);
        out[base + (size_t)s * DD] = h;
    }
}

// ---------------------------------------------------------------------------
extern "C" void kernel_launch(void* const* d_in, const int* in_sizes, int n_in,
                              void* d_out, int out_size)
{
    const float* x = (const float*)d_in[0];   // [B, S, D]
    const float* W = (const float*)d_in[1];   // [D, 3D]
    float* out = (float*)d_out;

    cudaFuncSetAttribute(gemm_gates_kernel,
                         cudaFuncAttributeMaxDynamicSharedMemorySize, DYN_BYTES);

    convert_x_kernel<<<(MM * DD / 4) / 256, 256>>>(x);
    convert_w_kernel<<<dim3(N3 / 32, DD / 32), dim3(32, 8)>>>(W);
    gemm_gates_kernel<<<dim3(DD / TNT, MM / TMT), 256, DYN_BYTES>>>();
    scan_partial_kernel<<<dim3(SCAN_C, BB), DD>>>();
    scan_combine_kernel<<<BB, DD>>>();
    scan_final_kernel<<<dim3(SCAN_C, BB), DD>>>(out);
}

// round 17
// speedup vs baseline: 1.0608x; 1.0608x over previous
#include <cuda_runtime.h>
#include <cuda_bf16.h>
#include <cuda_fp16.h>
#include <cstdint>

// ---------------------------------------------------------------------------
// Problem constants
// ---------------------------------------------------------------------------
#define BB 4
#define SS 8192
#define DD 1024
#define MM (BB * SS)      // 32768
#define N3 (3 * DD)       // 3072

// Scan chunking
#define SCAN_C 32
#define SCAN_L (SS / SCAN_C)   // 256
#define NCH (BB * DD)          // 4096

// GEMM tiling (R14 configuration — best measured)
#define TMT 128            // CTA M tile
#define TNT 64             // CTA N (d) tile per gate
#define KC 64              // fp16 K per chunk (128B rows)
#define NCHUNK 16          // single pass over K=1024
#define ROWB 144           // padded row bytes (128 data + 16 pad) -> conflict-free ldmatrix
#define A_BYTES (TMT * ROWB)          // 18432
#define BG_BYTES (TNT * ROWB)         // 9216
#define STAGEB (A_BYTES + 3 * BG_BYTES)  // 46080
#define DYN_BYTES (2 * STAGEB)        // 92160

// ---------------------------------------------------------------------------
// Scratch (static device allocations)
// ---------------------------------------------------------------------------
__device__ __half g_xh[(size_t)MM * DD];
__device__ __half g_wh[(size_t)N3 * DD];          // transposed: [n][k]
__device__ __half2 g_fv[(size_t)MM * DD];         // packed (f', val) per element
__device__ float g_pF[SCAN_C * NCH];
__device__ float g_pH[SCAN_C * NCH];
__device__ float g_carry[SCAN_C * NCH];

// ---------------------------------------------------------------------------
// Portable PTX helpers (valid on plain sm_103 target)
// ---------------------------------------------------------------------------
__device__ __forceinline__ uint32_t smem_u32(const void* p) {
    uint32_t a;
    asm("{ .reg .u64 t; cvta.to.shared.u64 t, %1; cvt.u32.u64 %0, t; }" : "=r"(a) : "l"(p));
    return a;
}
__device__ __forceinline__ void cpa16(uint32_t s, const void* g) {
    asm volatile("cp.async.cg.shared.global [%0], [%1], 16;" :: "r"(s), "l"(g));
}
__device__ __forceinline__ void ldmatrix_x4(uint32_t* r, uint32_t addr) {
    asm volatile("ldmatrix.sync.aligned.m8n8.x4.shared.b16 {%0,%1,%2,%3}, [%4];"
                 : "=r"(r[0]), "=r"(r[1]), "=r"(r[2]), "=r"(r[3]) : "r"(addr));
}
__device__ __forceinline__ void mma_fp16(float* c, const uint32_t* a, uint32_t b0, uint32_t b1) {
    asm volatile(
        "mma.sync.aligned.m16n8k16.row.col.f32.f16.f16.f32 "
        "{%0,%1,%2,%3}, {%4,%5,%6,%7}, {%8,%9}, {%0,%1,%2,%3};"
        : "+f"(c[0]), "+f"(c[1]), "+f"(c[2]), "+f"(c[3])
        : "r"(a[0]), "r"(a[1]), "r"(a[2]), "r"(a[3]), "r"(b0), "r"(b1));
}
__device__ __forceinline__ float rcp_fast(float x) {
    float y;
    asm("rcp.approx.ftz.f32 %0, %1;" : "=f"(y) : "f"(x));
    return y;
}

// ---------------------------------------------------------------------------
// Convert X -> fp16
// ---------------------------------------------------------------------------
__global__ __launch_bounds__(256) void convert_x_kernel(const float* __restrict__ X) {
    size_t i = (size_t)blockIdx.x * blockDim.x + threadIdx.x;   // float4 index
    float4 v = ((const float4*)X)[i];
    __half2* ph = (__half2*)g_xh;
    ph[2 * i]     = __floats2half2_rn(v.x, v.y);
    ph[2 * i + 1] = __floats2half2_rn(v.z, v.w);
}

// ---------------------------------------------------------------------------
// Convert + transpose W [K=1024, N=3072] -> Wt [N=3072, K=1024] fp16
// ---------------------------------------------------------------------------
__global__ __launch_bounds__(256) void convert_w_kernel(const float* __restrict__ W) {
    __shared__ float tile[32][33];
    int bx = blockIdx.x;   // n tile (96)
    int by = blockIdx.y;   // k tile (32)
    int tx = threadIdx.x;  // 32
    int ty = threadIdx.y;  // 8
#pragma unroll
    for (int i = 0; i < 4; ++i) {
        int k = by * 32 + ty + i * 8;
        tile[ty + i * 8][tx] = W[(size_t)k * N3 + bx * 32 + tx];
    }
    __syncthreads();
#pragma unroll
    for (int i = 0; i < 4; ++i) {
        int n = bx * 32 + ty + i * 8;
        int k = by * 32 + tx;
        g_wh[(size_t)n * DD + k] = __float2half_rn(tile[tx][ty + i * 8]);
    }
}

// ---------------------------------------------------------------------------
// Issue cp.async loads for one K-chunk (KC=64 -> 128B per row) into a stage.
// ---------------------------------------------------------------------------
__device__ __forceinline__ void load_chunk(int c, uint32_t sb, int tid, int m0, int n0) {
    const int kk = c * KC;

    // A: 128 rows x 128B (1024 x 16B, 4 per thread)
#pragma unroll
    for (int it = 0; it < 4; ++it) {
        int id = tid + it * 256;
        int r = id >> 3, ch = id & 7;
        cpa16(sb + r * ROWB + ch * 16,
              g_xh + (size_t)(m0 + r) * DD + kk + ch * 8);
    }
    // B: 3 gates x 64 rows x 128B (512 x 16B per gate, 2 per thread)
#pragma unroll
    for (int g = 0; g < 3; ++g) {
#pragma unroll
        for (int it = 0; it < 2; ++it) {
            int id = tid + it * 256;
            int r = id >> 3, ch = id & 7;
            cpa16(sb + A_BYTES + g * BG_BYTES + r * ROWB + ch * 16,
                  g_wh + (size_t)(g * DD + n0 + r) * DD + kk + ch * 8);
        }
    }
    asm volatile("cp.async.commit_group;" ::: "memory");
}

// ---------------------------------------------------------------------------
// fp16 mma.sync GEMM + fused gate epilogue (linear domain).
// R6 protocol: double buffer, wait_group 1, MMA, sync, refill freed stage.
// CTA: 256 threads (8 warps, 4x2 m-x-n), tile M=128 x N=64, 3 gates.
// ---------------------------------------------------------------------------
__global__ __launch_bounds__(256, 2) void gemm_gates_kernel() {
    extern __shared__ char sm_raw[];
    const uint32_t sbase = smem_u32(sm_raw);

    const int tid = threadIdx.x;
    const int wid = tid >> 5;
    const int lane = tid & 31;
    const int m0 = blockIdx.y * TMT;
    const int n0 = blockIdx.x * TNT;
    const int mw = (wid >> 1) * 32;   // warp m offset in tile
    const int nw = (wid & 1) * 32;    // warp n offset in tile

    // Per-lane ldmatrix address terms
    const int mat = lane >> 3;
    const uint32_t a_term = (uint32_t)((mw + (mat & 1) * 8 + (lane & 7)) * ROWB + (mat >> 1) * 16);
    const uint32_t b_term = (uint32_t)((nw + (mat >> 1) * 8 + (lane & 7)) * ROWB + (mat & 1) * 16);

    float acc[3][2][4][4];
#pragma unroll
    for (int g = 0; g < 3; ++g)
#pragma unroll
        for (int mt = 0; mt < 2; ++mt)
#pragma unroll
            for (int nt = 0; nt < 4; ++nt)
#pragma unroll
                for (int e = 0; e < 4; ++e) acc[g][mt][nt][e] = 0.0f;

    // Prologue: prefetch chunks 0,1
    load_chunk(0, sbase + 0 * STAGEB, tid, m0, n0);
    load_chunk(1, sbase + 1 * STAGEB, tid, m0, n0);

    for (int c = 0; c < NCHUNK; ++c) {
        asm volatile("cp.async.wait_group 1;" ::: "memory");
        __syncthreads();

        const uint32_t sb = sbase + (c & 1) * STAGEB;
#pragma unroll
        for (int ks = 0; ks < 4; ++ks) {
            // Preload ALL fragments for this ks first (8 independent ldmatrix),
            // then issue the 24 MMAs — maximizes ldsm->mma distance.
            uint32_t a[2][4];
            uint32_t b[3][2][4];
#pragma unroll
            for (int mt = 0; mt < 2; ++mt)
                ldmatrix_x4(a[mt], sb + a_term + mt * 16 * ROWB + ks * 32);
#pragma unroll
            for (int g = 0; g < 3; ++g) {
                const uint32_t bg = sb + A_BYTES + g * BG_BYTES + b_term + ks * 32;
#pragma unroll
                for (int j = 0; j < 2; ++j)
                    ldmatrix_x4(b[g][j], bg + j * 16 * ROWB);
            }
#pragma unroll
            for (int g = 0; g < 3; ++g)
#pragma unroll
                for (int mt = 0; mt < 2; ++mt)
#pragma unroll
                    for (int nt = 0; nt < 4; ++nt)
                        mma_fp16(acc[g][mt][nt], a[mt], b[g][nt >> 1][(nt & 1) * 2],
                                 b[g][nt >> 1][(nt & 1) * 2 + 1]);
        }
        __syncthreads();   // all warps done reading this stage

        if (c + 2 < NCHUNK) {
            load_chunk(c + 2, sb, tid, m0, n0);   // refill the freed stage
        } else {
            asm volatile("cp.async.commit_group;" ::: "memory");
        }
    }

    // ------------------------------------------------------------------
    // Epilogue: gate math in linear domain, packed half2(f', val).
    //   u = 1+e^{-f}, v = 1+e^{-i}, r = 1/(u+v)   (rcp.approx)
    //   f' = v*r, i' = u*r, g = (h>=0) ? h+0.5 : sigmoid(h), val = i'*g
    // ------------------------------------------------------------------
    const int rbase = lane >> 2;           // 0..7
    const int cbase = 2 * (lane & 3);      // 0,2,4,6
#pragma unroll
    for (int mt = 0; mt < 2; ++mt) {
#pragma unroll
        for (int nt = 0; nt < 4; ++nt) {
#pragma unroll
            for (int half = 0; half < 2; ++half) {
                const int m = m0 + mw + mt * 16 + rbase + half * 8;
                const int d = n0 + nw + nt * 8 + cbase;
                uint2 st;
#pragma unroll
                for (int e = 0; e < 2; ++e) {
                    const int ei = half * 2 + e;
                    float h  = acc[0][mt][nt][ei];
                    float fg = acc[1][mt][nt][ei];
                    float ig = acc[2][mt][nt][ei];
                    float u = 1.0f + __expf(-fg);
                    float v = 1.0f + __expf(-ig);
                    float r = rcp_fast(u + v);
                    float fp = v * r;
                    float ip = u * r;
                    float eh = __expf(fminf(h, 0.0f));
                    float gneg = eh * rcp_fast(1.0f + eh);
                    float gv = (h >= 0.0f) ? (h + 0.5f) : gneg;
                    __half2 pk = __floats2half2_rn(fp, ip * gv);
                    ((uint32_t*)&st)[e] = *(uint32_t*)&pk;
                }
                *(uint2*)&g_fv[(size_t)m * DD + d] = st;
            }
        }
    }
}

// ---------------------------------------------------------------------------
// Linear-domain scan on packed half2 (f', val): h = f*h + val
// ---------------------------------------------------------------------------
__global__ __launch_bounds__(1024) void scan_partial_kernel() {
    int d = threadIdx.x;
    int c = blockIdx.x;
    int b = blockIdx.y;
    size_t base = ((size_t)b * SS + (size_t)c * SCAN_L) * DD + d;
    float F = 1.0f;
    float H = 0.0f;
    for (int s = 0; s < SCAN_L; ++s) {
        float2 p = __half22float2(g_fv[base + (size_t)s * DD]);
        F *= p.x;
        H = fmaf(p.x, H, p.y);
    }
    int ch = b * DD + d;
    g_pF[c * NCH + ch] = F;
    g_pH[c * NCH + ch] = H;
}

__global__ __launch_bounds__(1024) void scan_combine_kernel() {
    int d = threadIdx.x;
    int b = blockIdx.x;
    int ch = b * DD + d;
    float st = 0.0f;
#pragma unroll
    for (int c = 0; c < SCAN_C; ++c) {
        g_carry[c * NCH + ch] = st;
        st = fmaf(g_pF[c * NCH + ch], st, g_pH[c * NCH + ch]);
    }
}

__global__ __launch_bounds__(1024) void scan_final_kernel(float* __restrict__ out) {
    int d = threadIdx.x;
    int c = blockIdx.x;
    int b = blockIdx.y;
    int ch = b * DD + d;
    float h = g_carry[c * NCH + ch];
    size_t base = ((size_t)b * SS + (size_t)c * SCAN_L) * DD + d;
    for (int s = 0; s < SCAN_L; ++s) {
        float2 p = __half22float2(g_fv[base + (size_t)s * DD]);
        h = fmaf(p.x, h, p.y);
        out[base + (size_t)s * DD] = h;
    }
}

// ---------------------------------------------------------------------------
extern "C" void kernel_launch(void* const* d_in, const int* in_sizes, int n_in,
                              void* d_out, int out_size)
{
    const float* x = (const float*)d_in[0];   // [B, S, D]
    const float* W = (const float*)d_in[1];   // [D, 3D]
    float* out = (float*)d_out;

    cudaFuncSetAttribute(gemm_gates_kernel,
                         cudaFuncAttributeMaxDynamicSharedMemorySize, DYN_BYTES);

    convert_x_kernel<<<(MM * DD / 4) / 256, 256>>>(x);
    convert_w_kernel<<<dim3(N3 / 32, DD / 32), dim3(32, 8)>>>(W);
    gemm_gates_kernel<<<dim3(DD / TNT, MM / TMT), 256, DYN_BYTES>>>();
    scan_partial_kernel<<<dim3(SCAN_C, BB), DD>>>();
    scan_combine_kernel<<<BB, DD>>>();
    scan_final_kernel<<<dim3(SCAN_C, BB), DD>>>(out);
}